// round 1
// baseline (speedup 1.0000x reference)
#include <cuda_runtime.h>
#include <math.h>
#include <math_constants.h>

// ---------------- problem constants ----------------
#define BATCH      4
#define SEQ        512
#define HID        1024
#define HS         64          // head size
#define ENT_HEADS  2
#define REL_HEADS  24
#define TOT_HEADS  (ENT_HEADS + 2 * REL_HEADS)   // 50
#define N_ENT      (ENT_HEADS * 2 * HS)          // 256
#define N_REL      (REL_HEADS * 2 * HS)          // 3072
#define N_TOT      (N_ENT + 2 * N_REL)           // 6400
#define TOKENS     (BATCH * SEQ)                 // 2048
#define MAX_LEN    1024

// ---------------- device scratch (no runtime alloc allowed) ----------------
__device__ float g_seq[TOKENS * N_TOT];                       // projection output, [token][6400]
__device__ float g_q[BATCH * TOT_HEADS * SEQ * HS];           // rotated Q, [(b*50+g)][s][64]
__device__ float g_k[BATCH * TOT_HEADS * SEQ * HS];           // rotated K
__device__ float g_cos[MAX_LEN * 16];                         // rope tables [pos][a]
__device__ float g_sin[MAX_LEN * 16];

// ---------------- kernel 0: rope tables (mirror jnp fp32 math) ----------------
__global__ void rope_table_kernel() {
    int t = blockIdx.x * blockDim.x + threadIdx.x;   // 1024*16 = 16384
    if (t >= MAX_LEN * 16) return;
    int pos = t >> 4;
    int a   = t & 15;
    // div = exp( (2a) * (-log(10000)/32) )
    float div = expf((float)(2 * a) * (-logf(10000.0f) / 32.0f));
    float ang = (float)pos * div;
    g_cos[t] = cosf(ang);
    g_sin[t] = sinf(ang);
}

// ---------------- kernel 1: SGEMM with bias, C = X(2048x1024) @ W(1024xN) + b ----------------
// C written into g_seq at column offset, ldc = 6400. 128x128 tile, BK=8, 256 thr, 8x8 per thread.
__global__ __launch_bounds__(256)
void sgemm_bias_kernel(const float* __restrict__ X, const float* __restrict__ W,
                       const float* __restrict__ bias, float* __restrict__ C,
                       int N, int ldc) {
    const int K = HID;
    __shared__ float As[8][128];
    __shared__ float Bs[8][128];

    int tid  = threadIdx.x;
    int trow = tid >> 4;          // 0..15
    int tcol = tid & 15;          // 0..15
    int m0 = blockIdx.y * 128;
    int n0 = blockIdx.x * 128;

    float acc[8][8];
#pragma unroll
    for (int i = 0; i < 8; ++i)
#pragma unroll
        for (int j = 0; j < 8; ++j) acc[i][j] = 0.0f;

    int arow = tid >> 1;                  // 0..127
    int acol = (tid & 1) * 4;             // 0 or 4
    int brow = tid >> 5;                  // 0..7
    int bcol = (tid & 31) * 4;            // 0..124

    const float* Xp = X + (size_t)(m0 + arow) * K + acol;
    const float* Wp = W + (size_t)brow * N + n0 + bcol;

    for (int k0 = 0; k0 < K; k0 += 8) {
        float4 a4 = *(const float4*)(Xp + k0);
        As[acol + 0][arow] = a4.x;
        As[acol + 1][arow] = a4.y;
        As[acol + 2][arow] = a4.z;
        As[acol + 3][arow] = a4.w;
        float4 b4 = *(const float4*)(Wp + (size_t)k0 * N);
        *(float4*)&Bs[brow][bcol] = b4;
        __syncthreads();

#pragma unroll
        for (int kk = 0; kk < 8; ++kk) {
            float a[8], b[8];
            *(float4*)(a)     = *(const float4*)&As[kk][trow * 8];
            *(float4*)(a + 4) = *(const float4*)&As[kk][trow * 8 + 4];
            *(float4*)(b)     = *(const float4*)&Bs[kk][tcol * 8];
            *(float4*)(b + 4) = *(const float4*)&Bs[kk][tcol * 8 + 4];
#pragma unroll
            for (int i = 0; i < 8; ++i)
#pragma unroll
                for (int j = 0; j < 8; ++j)
                    acc[i][j] = fmaf(a[i], b[j], acc[i][j]);
        }
        __syncthreads();
    }

    // epilogue: add bias, vector-store
    float bv[8];
#pragma unroll
    for (int j = 0; j < 8; ++j) bv[j] = bias[n0 + tcol * 8 + j];

#pragma unroll
    for (int i = 0; i < 8; ++i) {
        int row = m0 + trow * 8 + i;
        float* cp = C + (size_t)row * ldc + n0 + tcol * 8;
        float4 v0, v1;
        v0.x = acc[i][0] + bv[0]; v0.y = acc[i][1] + bv[1];
        v0.z = acc[i][2] + bv[2]; v0.w = acc[i][3] + bv[3];
        v1.x = acc[i][4] + bv[4]; v1.y = acc[i][5] + bv[5];
        v1.z = acc[i][6] + bv[6]; v1.w = acc[i][7] + bv[7];
        *(float4*)(cp)     = v0;
        *(float4*)(cp + 4) = v1;
    }
}

// ---------------- kernel 2: RoPE scatter  ----------------
// one thread per (token, head g, q/k, pair).  total = 2048*50*2*32 = 6,553,600
__global__ __launch_bounds__(256)
void rope_kernel(const int* __restrict__ xp, const int* __restrict__ yp) {
    unsigned t = blockIdx.x * 256u + threadIdx.x;
    int pair  = t & 31;
    int qk    = (t >> 5) & 1;
    unsigned r = t >> 6;
    int g     = r % 50;
    int token = r / 50;

    int base, hl;
    if (g < ENT_HEADS)                { base = 0;              hl = g; }
    else if (g < ENT_HEADS + REL_HEADS){ base = N_ENT;          hl = g - ENT_HEADS; }
    else                              { base = N_ENT + N_REL;  hl = g - ENT_HEADS - REL_HEADS; }

    int col = base + hl * (2 * HS) + qk * HS + pair * 2;
    const float* src = g_seq + (size_t)token * N_TOT + col;
    float2 v = *(const float2*)src;

    int p = (pair < 16) ? xp[token] : yp[token];
    int a = pair & 15;
    float c  = g_cos[p * 16 + a];
    float sn = g_sin[p * 16 + a];

    float o0 = v.x * c - v.y * sn;
    float o1 = v.y * c + v.x * sn;

    int b = token >> 9;
    int s = token & 511;
    size_t dst = (((size_t)(b * TOT_HEADS + g)) * SEQ + s) * HS + pair * 2;
    float* dp = (qk == 0) ? g_q : g_k;
    *(float2*)(dp + dst) = make_float2(o0, o1);
}

// ---------------- kernel 3: logits = Q @ K^T with mask/tril/scale epilogue ----------------
// grid: (4 n-tiles, 4 m-tiles, 200 bh), 256 thr, 128x128 tile, K=64 in two 32-slices.
__global__ __launch_bounds__(256)
void logits_kernel(const int* __restrict__ mask, float* __restrict__ out) {
    __shared__ float Qs[32][128];
    __shared__ float Ks[32][128];

    int bh = blockIdx.z;
    int b  = bh / TOT_HEADS;
    int g  = bh % TOT_HEADS;
    int m0 = blockIdx.y * 128;
    int n0 = blockIdx.x * 128;
    int tid = threadIdx.x;

    const float* Qb = g_q + (size_t)bh * SEQ * HS;
    const float* Kb = g_k + (size_t)bh * SEQ * HS;

    float acc[8][8];
#pragma unroll
    for (int i = 0; i < 8; ++i)
#pragma unroll
        for (int j = 0; j < 8; ++j) acc[i][j] = 0.0f;

    int trow = tid >> 4;
    int tcol = tid & 15;

    for (int kh = 0; kh < 2; ++kh) {
#pragma unroll
        for (int it = 0; it < 4; ++it) {
            int flat = it * 256 + tid;   // 0..1023 float4 units (128 rows x 8 f4)
            int row  = flat >> 3;
            int k4   = (flat & 7) * 4;
            float4 q4 = *(const float4*)(Qb + (size_t)(m0 + row) * HS + kh * 32 + k4);
            Qs[k4 + 0][row] = q4.x; Qs[k4 + 1][row] = q4.y;
            Qs[k4 + 2][row] = q4.z; Qs[k4 + 3][row] = q4.w;
            float4 k4v = *(const float4*)(Kb + (size_t)(n0 + row) * HS + kh * 32 + k4);
            Ks[k4 + 0][row] = k4v.x; Ks[k4 + 1][row] = k4v.y;
            Ks[k4 + 2][row] = k4v.z; Ks[k4 + 3][row] = k4v.w;
        }
        __syncthreads();

#pragma unroll
        for (int kk = 0; kk < 32; ++kk) {
            float a[8], bb[8];
            *(float4*)(a)      = *(const float4*)&Qs[kk][trow * 8];
            *(float4*)(a + 4)  = *(const float4*)&Qs[kk][trow * 8 + 4];
            *(float4*)(bb)     = *(const float4*)&Ks[kk][tcol * 8];
            *(float4*)(bb + 4) = *(const float4*)&Ks[kk][tcol * 8 + 4];
#pragma unroll
            for (int i = 0; i < 8; ++i)
#pragma unroll
                for (int j = 0; j < 8; ++j)
                    acc[i][j] = fmaf(a[i], bb[j], acc[i][j]);
        }
        __syncthreads();
    }

    // epilogue: mask (-inf), tril (ent heads), scale 1/8
    const int* mrow = mask + b * SEQ;
    bool pn[8];
#pragma unroll
    for (int j = 0; j < 8; ++j) pn[j] = (mrow[n0 + tcol * 8 + j] > 0);
    bool is_ent = (g < ENT_HEADS);

#pragma unroll
    for (int i = 0; i < 8; ++i) {
        int m = m0 + trow * 8 + i;
        bool pm = (mrow[m] > 0);
        float vals[8];
#pragma unroll
        for (int j = 0; j < 8; ++j) {
            int n = n0 + tcol * 8 + j;
            float v = acc[i][j];
            if (!(pm && pn[j])) v = -CUDART_INF_F;
            if (is_ent && m > n) v -= 1e12f;
            vals[j] = v * 0.125f;
        }
        float* op = out + (((size_t)(b * TOT_HEADS + g)) * SEQ + m) * SEQ + n0 + tcol * 8;
        *(float4*)(op)     = make_float4(vals[0], vals[1], vals[2], vals[3]);
        *(float4*)(op + 4) = make_float4(vals[4], vals[5], vals[6], vals[7]);
    }
}

// ---------------- launch ----------------
extern "C" void kernel_launch(void* const* d_in, const int* in_sizes, int n_in,
                              void* d_out, int out_size) {
    const float* x      = (const float*)d_in[0];
    const int*   mask   = (const int*)  d_in[1];
    const int*   xp     = (const int*)  d_in[2];
    const int*   yp     = (const int*)  d_in[3];
    const float* W_ent  = (const float*)d_in[4];
    const float* b_ent  = (const float*)d_in[5];
    const float* W_head = (const float*)d_in[6];
    const float* b_head = (const float*)d_in[7];
    const float* W_tail = (const float*)d_in[8];
    const float* b_tail = (const float*)d_in[9];
    float* out = (float*)d_out;

    float* seq;
    cudaGetSymbolAddress((void**)&seq, g_seq);

    // rope tables
    rope_table_kernel<<<(MAX_LEN * 16 + 255) / 256, 256>>>();

    // projections: X @ W + b into g_seq column slices
    dim3 blk(256);
    sgemm_bias_kernel<<<dim3(N_ENT / 128, TOKENS / 128), blk>>>(x, W_ent,  b_ent,  seq,                 N_ENT, N_TOT);
    sgemm_bias_kernel<<<dim3(N_REL / 128, TOKENS / 128), blk>>>(x, W_head, b_head, seq + N_ENT,         N_REL, N_TOT);
    sgemm_bias_kernel<<<dim3(N_REL / 128, TOKENS / 128), blk>>>(x, W_tail, b_tail, seq + N_ENT + N_REL, N_REL, N_TOT);

    // rope: 2048 tokens * 50 heads * 2 (q/k) * 32 pairs
    rope_kernel<<<(TOKENS * TOT_HEADS * 2 * 32) / 256, 256>>>(xp, yp);

    // logits
    logits_kernel<<<dim3(SEQ / 128, SEQ / 128, BATCH * TOT_HEADS), blk>>>(mask, out);
}

// round 3
// speedup vs baseline: 2.7764x; 2.7764x over previous
#include <cuda_runtime.h>
#include <cuda_bf16.h>
#include <math.h>
#include <math_constants.h>
#include <cstdint>

// ---------------- problem constants ----------------
#define BATCH      4
#define SEQ        512
#define HID        1024
#define HS         64
#define ENT_HEADS  2
#define REL_HEADS  24
#define TOT_HEADS  (ENT_HEADS + 2 * REL_HEADS)   // 50
#define N_ENT      (ENT_HEADS * 2 * HS)          // 256
#define N_REL      (REL_HEADS * 2 * HS)          // 3072
#define N_TOT      (N_ENT + 2 * N_REL)           // 6400
#define TOKENS     (BATCH * SEQ)                 // 2048
#define MAX_LEN    1024
#define BH         (BATCH * TOT_HEADS)           // 200

// ---------------- device scratch ----------------
__device__ __nv_bfloat16 g_xhi[TOKENS * HID];
__device__ __nv_bfloat16 g_xlo[TOKENS * HID];
__device__ __nv_bfloat16 g_wthi[N_TOT * HID];   // transposed weights [n][k]
__device__ __nv_bfloat16 g_wtlo[N_TOT * HID];
__device__ __nv_bfloat16 g_qhi[BH * SEQ * HS];
__device__ __nv_bfloat16 g_qlo[BH * SEQ * HS];
__device__ __nv_bfloat16 g_khi[BH * SEQ * HS];
__device__ __nv_bfloat16 g_klo[BH * SEQ * HS];
__device__ float g_cos[MAX_LEN * 16];
__device__ float g_sin[MAX_LEN * 16];

// ---------------- ptx helpers (sm_80+ only: no tcgen05!) ----------------
__device__ __forceinline__ uint32_t smem_u32(const void* p) {
    uint32_t a;
    asm("{ .reg .u64 t; cvta.to.shared.u64 t, %1; cvt.u32.u64 %0, t; }" : "=r"(a) : "l"(p));
    return a;
}
__device__ __forceinline__ void cp16(uint32_t saddr, const void* g) {
    asm volatile("cp.async.cg.shared.global [%0], [%1], 16;" :: "r"(saddr), "l"(g) : "memory");
}
#define CP_COMMIT() asm volatile("cp.async.commit_group;" ::: "memory")

__device__ __forceinline__ void ldsm_x4(uint32_t* r, uint32_t addr) {
    asm volatile("ldmatrix.sync.aligned.m8n8.x4.shared.b16 {%0,%1,%2,%3}, [%4];"
        : "=r"(r[0]), "=r"(r[1]), "=r"(r[2]), "=r"(r[3]) : "r"(addr));
}
__device__ __forceinline__ void mma16816(float* c, const uint32_t* a, const uint32_t* b) {
    asm volatile(
        "mma.sync.aligned.m16n8k16.row.col.f32.bf16.bf16.f32 "
        "{%0,%1,%2,%3}, {%4,%5,%6,%7}, {%8,%9}, {%0,%1,%2,%3};"
        : "+f"(c[0]), "+f"(c[1]), "+f"(c[2]), "+f"(c[3])
        : "r"(a[0]), "r"(a[1]), "r"(a[2]), "r"(a[3]), "r"(b[0]), "r"(b[1]));
}

// ---------------- kernel 0: rope tables ----------------
__global__ void rope_table_kernel() {
    int t = blockIdx.x * blockDim.x + threadIdx.x;
    if (t >= MAX_LEN * 16) return;
    int pos = t >> 4;
    int a   = t & 15;
    float div = expf((float)(2 * a) * (-logf(10000.0f) / 32.0f));
    float ang = (float)pos * div;
    g_cos[t] = cosf(ang);
    g_sin[t] = sinf(ang);
}

// ---------------- kernel 1: X -> bf16 hi/lo ----------------
__global__ __launch_bounds__(256)
void convert_x_kernel(const float* __restrict__ X) {
    int i = blockIdx.x * 256 + threadIdx.x;
    if (i >= TOKENS * HID / 2) return;
    float2 v = ((const float2*)X)[i];
    __nv_bfloat16 h0 = __float2bfloat16(v.x);
    __nv_bfloat16 h1 = __float2bfloat16(v.y);
    __nv_bfloat16 l0 = __float2bfloat16(v.x - __bfloat162float(h0));
    __nv_bfloat16 l1 = __float2bfloat16(v.y - __bfloat162float(h1));
    ((__nv_bfloat162*)g_xhi)[i] = __halves2bfloat162(h0, h1);
    ((__nv_bfloat162*)g_xlo)[i] = __halves2bfloat162(l0, l1);
}

// ---------------- kernel 2: W[k][n] -> Wt hi/lo [n][k] ----------------
__global__ __launch_bounds__(256)
void convert_w_kernel(const float* __restrict__ W, int N, int coloff) {
    __shared__ float t[32][33];
    int n0 = blockIdx.x * 32;
    int k0 = blockIdx.y * 32;
    int tx = threadIdx.x, ty = threadIdx.y;   // block (32, 8)
#pragma unroll
    for (int i = 0; i < 4; ++i)
        t[ty + i * 8][tx] = W[(size_t)(k0 + ty + i * 8) * N + n0 + tx];
    __syncthreads();
#pragma unroll
    for (int i = 0; i < 4; ++i) {
        int n = n0 + ty + i * 8;
        float v = t[tx][ty + i * 8];
        __nv_bfloat16 h = __float2bfloat16(v);
        __nv_bfloat16 l = __float2bfloat16(v - __bfloat162float(h));
        size_t o = (size_t)(coloff + n) * HID + k0 + tx;
        g_wthi[o] = h;
        g_wtlo[o] = l;
    }
}

// ---------------- kernel 3: projection GEMM (HMMA hi/lo) + bias + RoPE ----------------
// CTA: 128 tokens x 128 cols (= ONE head: 64 q | 64 k). 8 warps 4x2, warp 32x64.
// smem per stage: Ahi | Alo | Bhi | Blo, each 128x40 bf16 = 10240B; 2 stages.
#define PJ_STRIDE 40
#define PJ_BUF    10240
#define PJ_STAGE  40960
#define PJ_SMEM   81920

extern __shared__ __align__(128) char dsm[];

__global__ __launch_bounds__(256)
void proj_mma_kernel(const float* __restrict__ bias,
                     const int* __restrict__ xp, const int* __restrict__ yp,
                     int wt_coloff, int head_off) {
    uint32_t sb = smem_u32(dsm);
    int tid = threadIdx.x, wid = tid >> 5, lane = tid & 31;
    int m0 = blockIdx.y * 128;
    int head = head_off + blockIdx.x;
    int warp_m = (wid & 3) * 32, warp_n = (wid >> 2) * 64;

    const __nv_bfloat16* Xh = g_xhi + (size_t)m0 * HID;
    const __nv_bfloat16* Xl = g_xlo + (size_t)m0 * HID;
    const __nv_bfloat16* Wh = g_wthi + (size_t)(wt_coloff + blockIdx.x * 128) * HID;
    const __nv_bfloat16* Wl = g_wtlo + (size_t)(wt_coloff + blockIdx.x * 128) * HID;

    float acc[2][8][4];
#pragma unroll
    for (int i = 0; i < 2; ++i)
#pragma unroll
        for (int j = 0; j < 8; ++j)
#pragma unroll
            for (int k = 0; k < 4; ++k) acc[i][j][k] = 0.0f;

    // ldmatrix lane geometry
    int a_row = (lane & 7) + ((lane >> 3) & 1) * 8;
    int a_col = (lane >> 4) * 8;
    int b_row = (lane & 7) + ((lane >> 4) & 1) * 8;
    int b_col = ((lane >> 3) & 1) * 8;

    // gmem->smem mapping (per stage: 512 x 16B per buffer, 2 per thread)
    int r0 = tid >> 1;            // wrong granularity avoided below; use flat loop
    (void)r0;

#define PJ_ISSUE(stage, c) do {                                               \
    int k0 = (c) * 32;                                                        \
    uint32_t base = sb + (stage) * PJ_STAGE;                                  \
    _Pragma("unroll")                                                         \
    for (int it = 0; it < 2; ++it) {                                          \
        int flat = it * 256 + tid;                                            \
        int rr = flat >> 2, jj = flat & 3;                                    \
        uint32_t so = (uint32_t)(rr * PJ_STRIDE + jj * 8) * 2;                \
        size_t go = (size_t)rr * HID + k0 + jj * 8;                           \
        cp16(base + so,              Xh + go);                                \
        cp16(base + PJ_BUF + so,     Xl + go);                                \
        cp16(base + 2 * PJ_BUF + so, Wh + go);                                \
        cp16(base + 3 * PJ_BUF + so, Wl + go);                                \
    }                                                                         \
    CP_COMMIT();                                                              \
} while (0)

    PJ_ISSUE(0, 0);
    for (int c = 0; c < 32; ++c) {
        int st = c & 1;
        if (c + 1 < 32) {
            PJ_ISSUE(st ^ 1, c + 1);
            asm volatile("cp.async.wait_group 1;" ::: "memory");
        } else {
            asm volatile("cp.async.wait_group 0;" ::: "memory");
        }
        __syncthreads();

        uint32_t bA = sb + st * PJ_STAGE;
#pragma unroll
        for (int k16 = 0; k16 < 32; k16 += 16) {
            uint32_t ah[2][4], al[2][4];
#pragma unroll
            for (int mi = 0; mi < 2; ++mi) {
                uint32_t ao = (uint32_t)((warp_m + mi * 16 + a_row) * PJ_STRIDE + a_col + k16) * 2;
                ldsm_x4(ah[mi], bA + ao);
                ldsm_x4(al[mi], bA + PJ_BUF + ao);
            }
#pragma unroll
            for (int n2 = 0; n2 < 4; ++n2) {
                uint32_t bh[4], bl[4];
                uint32_t bo = (uint32_t)((warp_n + n2 * 16 + b_row) * PJ_STRIDE + b_col + k16) * 2;
                ldsm_x4(bh, bA + 2 * PJ_BUF + bo);
                ldsm_x4(bl, bA + 3 * PJ_BUF + bo);
#pragma unroll
                for (int mi = 0; mi < 2; ++mi)
#pragma unroll
                    for (int t = 0; t < 2; ++t) {
                        float* C = acc[mi][n2 * 2 + t];
                        mma16816(C, ah[mi], bh + 2 * t);
                        mma16816(C, ah[mi], bl + 2 * t);
                        mma16816(C, al[mi], bh + 2 * t);
                    }
            }
        }
        __syncthreads();
    }

    // ---- epilogue: bias + 2D RoPE, split to bf16 hi/lo, write g_q*/g_k* ----
    int qk = warp_n >> 6;                       // 0 = q half, 1 = k half
    __nv_bfloat16* ohi = qk ? g_khi : g_qhi;
    __nv_bfloat16* olo = qk ? g_klo : g_qlo;
#pragma unroll
    for (int mi = 0; mi < 2; ++mi) {
#pragma unroll
        for (int h = 0; h < 2; ++h) {
            int row = m0 + warp_m + mi * 16 + (lane >> 2) + h * 8;
            int px = xp[row], py = yp[row];
            int b = row >> 9, s = row & 511;
            size_t obase = ((size_t)(b * TOT_HEADS + head) * SEQ + s) * HS;
#pragma unroll
            for (int ni = 0; ni < 8; ++ni) {
                int d = ni * 8 + 2 * (lane & 3);          // 0..62 even, within 64-col half
                float v0 = acc[mi][ni][h * 2 + 0] + bias[blockIdx.x * 128 + warp_n + d];
                float v1 = acc[mi][ni][h * 2 + 1] + bias[blockIdx.x * 128 + warp_n + d + 1];
                int p = (d < 32) ? px : py;
                int a = (d & 31) >> 1;
                float cc = g_cos[p * 16 + a], sn = g_sin[p * 16 + a];
                float o0 = v0 * cc - v1 * sn;
                float o1 = v1 * cc + v0 * sn;
                __nv_bfloat16 h0 = __float2bfloat16(o0);
                __nv_bfloat16 h1 = __float2bfloat16(o1);
                __nv_bfloat16 l0 = __float2bfloat16(o0 - __bfloat162float(h0));
                __nv_bfloat16 l1 = __float2bfloat16(o1 - __bfloat162float(h1));
                *(__nv_bfloat162*)(ohi + obase + d) = __halves2bfloat162(h0, h1);
                *(__nv_bfloat162*)(olo + obase + d) = __halves2bfloat162(l0, l1);
            }
        }
    }
}

// ---------------- kernel 4: logits = Q @ K^T (HMMA hi/lo) + mask/tril/scale ----------------
// CTA 128x128, K=64 loaded once. smem: Qhi|Qlo|Khi|Klo each 128x72 bf16 = 18432B.
#define LG_STRIDE 72
#define LG_BUF    18432
#define LG_SMEM   73728

__global__ __launch_bounds__(256)
void logits_mma_kernel(const int* __restrict__ mask, float* __restrict__ out) {
    uint32_t sb = smem_u32(dsm);
    int tid = threadIdx.x, wid = tid >> 5, lane = tid & 31;
    int bh = blockIdx.z;
    int b = bh / TOT_HEADS, g = bh % TOT_HEADS;
    int m0 = blockIdx.y * 128, n0 = blockIdx.x * 128;
    int warp_m = (wid & 3) * 32, warp_n = (wid >> 2) * 64;

    const __nv_bfloat16* Qh = g_qhi + (size_t)bh * SEQ * HS;
    const __nv_bfloat16* Ql = g_qlo + (size_t)bh * SEQ * HS;
    const __nv_bfloat16* Kh = g_khi + (size_t)bh * SEQ * HS;
    const __nv_bfloat16* Kl = g_klo + (size_t)bh * SEQ * HS;

#pragma unroll
    for (int it = 0; it < 4; ++it) {
        int flat = it * 256 + tid;            // 1024 x 16B per buffer
        int r = flat >> 3, j = flat & 7;
        uint32_t so = (uint32_t)(r * LG_STRIDE + j * 8) * 2;
        cp16(sb + so,              Qh + (size_t)(m0 + r) * HS + j * 8);
        cp16(sb + LG_BUF + so,     Ql + (size_t)(m0 + r) * HS + j * 8);
        cp16(sb + 2 * LG_BUF + so, Kh + (size_t)(n0 + r) * HS + j * 8);
        cp16(sb + 3 * LG_BUF + so, Kl + (size_t)(n0 + r) * HS + j * 8);
    }
    CP_COMMIT();
    asm volatile("cp.async.wait_group 0;" ::: "memory");
    __syncthreads();

    float acc[2][8][4];
#pragma unroll
    for (int i = 0; i < 2; ++i)
#pragma unroll
        for (int j = 0; j < 8; ++j)
#pragma unroll
            for (int k = 0; k < 4; ++k) acc[i][j][k] = 0.0f;

    int a_row = (lane & 7) + ((lane >> 3) & 1) * 8;
    int a_col = (lane >> 4) * 8;
    int b_row = (lane & 7) + ((lane >> 4) & 1) * 8;
    int b_col = ((lane >> 3) & 1) * 8;

#pragma unroll
    for (int k16 = 0; k16 < 64; k16 += 16) {
        uint32_t ah[2][4], al[2][4];
#pragma unroll
        for (int mi = 0; mi < 2; ++mi) {
            uint32_t ao = (uint32_t)((warp_m + mi * 16 + a_row) * LG_STRIDE + a_col + k16) * 2;
            ldsm_x4(ah[mi], sb + ao);
            ldsm_x4(al[mi], sb + LG_BUF + ao);
        }
#pragma unroll
        for (int n2 = 0; n2 < 4; ++n2) {
            uint32_t bhf[4], blf[4];
            uint32_t bo = (uint32_t)((warp_n + n2 * 16 + b_row) * LG_STRIDE + b_col + k16) * 2;
            ldsm_x4(bhf, sb + 2 * LG_BUF + bo);
            ldsm_x4(blf, sb + 3 * LG_BUF + bo);
#pragma unroll
            for (int mi = 0; mi < 2; ++mi)
#pragma unroll
                for (int t = 0; t < 2; ++t) {
                    float* C = acc[mi][n2 * 2 + t];
                    mma16816(C, ah[mi], bhf + 2 * t);
                    mma16816(C, ah[mi], blf + 2 * t);
                    mma16816(C, al[mi], bhf + 2 * t);
                }
        }
    }

    // epilogue
    const int* mrow = mask + b * SEQ;
    bool is_ent = (g < ENT_HEADS);
#pragma unroll
    for (int mi = 0; mi < 2; ++mi) {
#pragma unroll
        for (int h = 0; h < 2; ++h) {
            int m = m0 + warp_m + mi * 16 + (lane >> 2) + h * 8;
            bool pm = (mrow[m] > 0);
            float* orow = out + ((size_t)bh * SEQ + m) * SEQ;
#pragma unroll
            for (int ni = 0; ni < 8; ++ni) {
                int n = n0 + warp_n + ni * 8 + 2 * (lane & 3);
                float v0 = acc[mi][ni][h * 2 + 0];
                float v1 = acc[mi][ni][h * 2 + 1];
                if (!(pm && mrow[n] > 0))     v0 = -CUDART_INF_F;
                if (!(pm && mrow[n + 1] > 0)) v1 = -CUDART_INF_F;
                if (is_ent) {
                    if (m > n)     v0 -= 1e12f;
                    if (m > n + 1) v1 -= 1e12f;
                }
                *(float2*)(orow + n) = make_float2(v0 * 0.125f, v1 * 0.125f);
            }
        }
    }
}

// ---------------- launch ----------------
extern "C" void kernel_launch(void* const* d_in, const int* in_sizes, int n_in,
                              void* d_out, int out_size) {
    const float* x      = (const float*)d_in[0];
    const int*   mask   = (const int*)  d_in[1];
    const int*   xp     = (const int*)  d_in[2];
    const int*   yp     = (const int*)  d_in[3];
    const float* W_ent  = (const float*)d_in[4];
    const float* b_ent  = (const float*)d_in[5];
    const float* W_head = (const float*)d_in[6];
    const float* b_head = (const float*)d_in[7];
    const float* W_tail = (const float*)d_in[8];
    const float* b_tail = (const float*)d_in[9];
    float* out = (float*)d_out;

    cudaFuncSetAttribute(proj_mma_kernel,   cudaFuncAttributeMaxDynamicSharedMemorySize, PJ_SMEM);
    cudaFuncSetAttribute(logits_mma_kernel, cudaFuncAttributeMaxDynamicSharedMemorySize, LG_SMEM);

    rope_table_kernel<<<(MAX_LEN * 16 + 255) / 256, 256>>>();
    convert_x_kernel<<<(TOKENS * HID / 2 + 255) / 256, 256>>>(x);

    dim3 tb(32, 8);
    convert_w_kernel<<<dim3(N_ENT / 32, HID / 32), tb>>>(W_ent,  N_ENT, 0);
    convert_w_kernel<<<dim3(N_REL / 32, HID / 32), tb>>>(W_head, N_REL, N_ENT);
    convert_w_kernel<<<dim3(N_REL / 32, HID / 32), tb>>>(W_tail, N_REL, N_ENT + N_REL);

    proj_mma_kernel<<<dim3(2,  TOKENS / 128), 256, PJ_SMEM>>>(b_ent,  xp, yp, 0,             0);
    proj_mma_kernel<<<dim3(24, TOKENS / 128), 256, PJ_SMEM>>>(b_head, xp, yp, N_ENT,         ENT_HEADS);
    proj_mma_kernel<<<dim3(24, TOKENS / 128), 256, PJ_SMEM>>>(b_tail, xp, yp, N_ENT + N_REL, ENT_HEADS + REL_HEADS);

    logits_mma_kernel<<<dim3(SEQ / 128, SEQ / 128, BH), 256, LG_SMEM>>>(mask, out);
}

// round 4
// speedup vs baseline: 6.1460x; 2.2136x over previous
#include <cuda_runtime.h>
#include <cuda_bf16.h>
#include <math.h>
#include <math_constants.h>
#include <cstdint>

// ---------------- problem constants ----------------
#define BATCH      4
#define SEQ        512
#define HID        1024
#define HS         64
#define ENT_HEADS  2
#define REL_HEADS  24
#define TOT_HEADS  (ENT_HEADS + 2 * REL_HEADS)   // 50
#define N_ENT      (ENT_HEADS * 2 * HS)          // 256
#define N_REL      (REL_HEADS * 2 * HS)          // 3072
#define N_TOT      (N_ENT + 2 * N_REL)           // 6400
#define TOKENS     (BATCH * SEQ)                 // 2048
#define MAX_LEN    1024
#define BH         (BATCH * TOT_HEADS)           // 200

// ---------------- device scratch ----------------
__device__ __nv_bfloat16 g_x[TOKENS * HID];
__device__ __nv_bfloat16 g_wt[N_TOT * HID];      // transposed weights [n][k]
__device__ __nv_bfloat16 g_q[BH * SEQ * HS];
__device__ __nv_bfloat16 g_k[BH * SEQ * HS];
__device__ float g_cos[MAX_LEN * 16];
__device__ float g_sin[MAX_LEN * 16];

// ---------------- ptx helpers (sm_80+ only: no tcgen05) ----------------
__device__ __forceinline__ uint32_t smem_u32(const void* p) {
    uint32_t a;
    asm("{ .reg .u64 t; cvta.to.shared.u64 t, %1; cvt.u32.u64 %0, t; }" : "=r"(a) : "l"(p));
    return a;
}
__device__ __forceinline__ void cp16(uint32_t saddr, const void* g) {
    asm volatile("cp.async.cg.shared.global [%0], [%1], 16;" :: "r"(saddr), "l"(g) : "memory");
}
#define CP_COMMIT() asm volatile("cp.async.commit_group;" ::: "memory")

__device__ __forceinline__ void ldsm_x4(uint32_t* r, uint32_t addr) {
    asm volatile("ldmatrix.sync.aligned.m8n8.x4.shared.b16 {%0,%1,%2,%3}, [%4];"
        : "=r"(r[0]), "=r"(r[1]), "=r"(r[2]), "=r"(r[3]) : "r"(addr));
}
__device__ __forceinline__ void mma16816(float* c, const uint32_t* a, const uint32_t* b) {
    asm volatile(
        "mma.sync.aligned.m16n8k16.row.col.f32.bf16.bf16.f32 "
        "{%0,%1,%2,%3}, {%4,%5,%6,%7}, {%8,%9}, {%0,%1,%2,%3};"
        : "+f"(c[0]), "+f"(c[1]), "+f"(c[2]), "+f"(c[3])
        : "r"(a[0]), "r"(a[1]), "r"(a[2]), "r"(a[3]), "r"(b[0]), "r"(b[1]));
}

// ---------------- kernel 0: rope tables ----------------
__global__ void rope_table_kernel() {
    int t = blockIdx.x * blockDim.x + threadIdx.x;
    if (t >= MAX_LEN * 16) return;
    int pos = t >> 4;
    int a   = t & 15;
    float div = expf((float)(2 * a) * (-logf(10000.0f) / 32.0f));
    float ang = (float)pos * div;
    g_cos[t] = cosf(ang);
    g_sin[t] = sinf(ang);
}

// ---------------- kernel 1: X -> bf16 ----------------
__global__ __launch_bounds__(256)
void convert_x_kernel(const float* __restrict__ X) {
    int i = blockIdx.x * 256 + threadIdx.x;
    if (i >= TOKENS * HID / 2) return;
    float2 v = ((const float2*)X)[i];
    ((__nv_bfloat162*)g_x)[i] =
        __halves2bfloat162(__float2bfloat16(v.x), __float2bfloat16(v.y));
}

// ---------------- kernel 2: W[k][n] -> Wt bf16 [n][k] ----------------
__global__ __launch_bounds__(256)
void convert_w_kernel(const float* __restrict__ W, int N, int coloff) {
    __shared__ float t[32][33];
    int n0 = blockIdx.x * 32;
    int k0 = blockIdx.y * 32;
    int tx = threadIdx.x, ty = threadIdx.y;   // block (32, 8)
#pragma unroll
    for (int i = 0; i < 4; ++i)
        t[ty + i * 8][tx] = W[(size_t)(k0 + ty + i * 8) * N + n0 + tx];
    __syncthreads();
#pragma unroll
    for (int i = 0; i < 4; ++i) {
        int n = n0 + ty + i * 8;
        g_wt[(size_t)(coloff + n) * HID + k0 + tx] = __float2bfloat16(t[tx][ty + i * 8]);
    }
}

// ---------------- kernel 3: projection GEMM (bf16 HMMA) + bias + RoPE ----------------
// CTA: 128 tokens x 128 cols (= ONE head: 64 q | 64 k). 8 warps 4x2, warp 32x64.
// BK=64, 2-stage cp.async. Per stage: A 128x72 bf16 (18432B) + B same. Stage=36864.
#define PJ_STRIDE 72
#define PJ_BUF    18432
#define PJ_STAGE  36864
#define PJ_SMEM   73728

extern __shared__ __align__(128) char dsm[];

__global__ __launch_bounds__(256)
void proj_mma_kernel(const float* __restrict__ bias,
                     const int* __restrict__ xp, const int* __restrict__ yp,
                     int wt_coloff, int head_off) {
    uint32_t sb = smem_u32(dsm);
    int tid = threadIdx.x, wid = tid >> 5, lane = tid & 31;
    int m0 = blockIdx.y * 128;
    int head = head_off + blockIdx.x;
    int warp_m = (wid & 3) * 32, warp_n = (wid >> 2) * 64;

    const __nv_bfloat16* Xp = g_x  + (size_t)m0 * HID;
    const __nv_bfloat16* Wp = g_wt + (size_t)(wt_coloff + blockIdx.x * 128) * HID;

    float acc[2][8][4];
#pragma unroll
    for (int i = 0; i < 2; ++i)
#pragma unroll
        for (int j = 0; j < 8; ++j)
#pragma unroll
            for (int k = 0; k < 4; ++k) acc[i][j][k] = 0.0f;

    int a_row = (lane & 7) + ((lane >> 3) & 1) * 8;
    int a_col = (lane >> 4) * 8;
    int b_row = (lane & 7) + ((lane >> 4) & 1) * 8;
    int b_col = ((lane >> 3) & 1) * 8;

#define PJ_ISSUE(stage, c) do {                                               \
    int k0 = (c) * 64;                                                        \
    uint32_t base = sb + (stage) * PJ_STAGE;                                  \
    _Pragma("unroll")                                                         \
    for (int it = 0; it < 4; ++it) {                                          \
        int flat = it * 256 + tid;           /* 1024 16B units per buffer */  \
        int rr = flat >> 3, jj = flat & 7;                                    \
        uint32_t so = (uint32_t)(rr * PJ_STRIDE + jj * 8) * 2;                \
        size_t go = (size_t)rr * HID + k0 + jj * 8;                           \
        cp16(base + so,          Xp + go);                                    \
        cp16(base + PJ_BUF + so, Wp + go);                                    \
    }                                                                         \
    CP_COMMIT();                                                              \
} while (0)

    PJ_ISSUE(0, 0);
    for (int c = 0; c < 16; ++c) {
        int st = c & 1;
        if (c + 1 < 16) {
            PJ_ISSUE(st ^ 1, c + 1);
            asm volatile("cp.async.wait_group 1;" ::: "memory");
        } else {
            asm volatile("cp.async.wait_group 0;" ::: "memory");
        }
        __syncthreads();

        uint32_t bA = sb + st * PJ_STAGE;
#pragma unroll
        for (int k16 = 0; k16 < 64; k16 += 16) {
            uint32_t ah[2][4];
#pragma unroll
            for (int mi = 0; mi < 2; ++mi) {
                uint32_t ao = (uint32_t)((warp_m + mi * 16 + a_row) * PJ_STRIDE + a_col + k16) * 2;
                ldsm_x4(ah[mi], bA + ao);
            }
#pragma unroll
            for (int n2 = 0; n2 < 4; ++n2) {
                uint32_t bh[4];
                uint32_t bo = (uint32_t)((warp_n + n2 * 16 + b_row) * PJ_STRIDE + b_col + k16) * 2;
                ldsm_x4(bh, bA + PJ_BUF + bo);
#pragma unroll
                for (int mi = 0; mi < 2; ++mi)
#pragma unroll
                    for (int t = 0; t < 2; ++t)
                        mma16816(acc[mi][n2 * 2 + t], ah[mi], bh + 2 * t);
            }
        }
        __syncthreads();
    }

    // ---- epilogue: bias + 2D RoPE, write bf16 q/k ----
    int qk = warp_n >> 6;                       // 0 = q half, 1 = k half
    __nv_bfloat16* outp = qk ? g_k : g_q;
#pragma unroll
    for (int mi = 0; mi < 2; ++mi) {
#pragma unroll
        for (int h = 0; h < 2; ++h) {
            int row = m0 + warp_m + mi * 16 + (lane >> 2) + h * 8;
            int px = xp[row], py = yp[row];
            int b = row >> 9, s = row & 511;
            size_t obase = ((size_t)(b * TOT_HEADS + head) * SEQ + s) * HS;
#pragma unroll
            for (int ni = 0; ni < 8; ++ni) {
                int d = ni * 8 + 2 * (lane & 3);          // 0..62 even
                float v0 = acc[mi][ni][h * 2 + 0] + bias[blockIdx.x * 128 + warp_n + d];
                float v1 = acc[mi][ni][h * 2 + 1] + bias[blockIdx.x * 128 + warp_n + d + 1];
                int p = (d < 32) ? px : py;
                int a = (d & 31) >> 1;
                float cc = g_cos[p * 16 + a], sn = g_sin[p * 16 + a];
                float o0 = v0 * cc - v1 * sn;
                float o1 = v1 * cc + v0 * sn;
                *(__nv_bfloat162*)(outp + obase + d) =
                    __halves2bfloat162(__float2bfloat16(o0), __float2bfloat16(o1));
            }
        }
    }
}

// ---------------- kernel 4: logits = Q @ K^T (bf16 HMMA) + mask/tril/scale ----------------
// CTA 128x128, K=64 loaded once. smem: Q | K each 128x72 bf16 = 18432B.
#define LG_STRIDE 72
#define LG_BUF    18432
#define LG_SMEM   36864

__global__ __launch_bounds__(256)
void logits_mma_kernel(const int* __restrict__ mask, float* __restrict__ out) {
    uint32_t sb = smem_u32(dsm);
    int tid = threadIdx.x, wid = tid >> 5, lane = tid & 31;
    int bh = blockIdx.z;
    int b = bh / TOT_HEADS, g = bh % TOT_HEADS;
    int m0 = blockIdx.y * 128, n0 = blockIdx.x * 128;
    int warp_m = (wid & 3) * 32, warp_n = (wid >> 2) * 64;

    const __nv_bfloat16* Qb = g_q + (size_t)bh * SEQ * HS;
    const __nv_bfloat16* Kb = g_k + (size_t)bh * SEQ * HS;

#pragma unroll
    for (int it = 0; it < 4; ++it) {
        int flat = it * 256 + tid;            // 1024 16B units per buffer
        int r = flat >> 3, j = flat & 7;
        uint32_t so = (uint32_t)(r * LG_STRIDE + j * 8) * 2;
        cp16(sb + so,          Qb + (size_t)(m0 + r) * HS + j * 8);
        cp16(sb + LG_BUF + so, Kb + (size_t)(n0 + r) * HS + j * 8);
    }
    CP_COMMIT();
    asm volatile("cp.async.wait_group 0;" ::: "memory");
    __syncthreads();

    float acc[2][8][4];
#pragma unroll
    for (int i = 0; i < 2; ++i)
#pragma unroll
        for (int j = 0; j < 8; ++j)
#pragma unroll
            for (int k = 0; k < 4; ++k) acc[i][j][k] = 0.0f;

    int a_row = (lane & 7) + ((lane >> 3) & 1) * 8;
    int a_col = (lane >> 4) * 8;
    int b_row = (lane & 7) + ((lane >> 4) & 1) * 8;
    int b_col = ((lane >> 3) & 1) * 8;

#pragma unroll
    for (int k16 = 0; k16 < 64; k16 += 16) {
        uint32_t ah[2][4];
#pragma unroll
        for (int mi = 0; mi < 2; ++mi) {
            uint32_t ao = (uint32_t)((warp_m + mi * 16 + a_row) * LG_STRIDE + a_col + k16) * 2;
            ldsm_x4(ah[mi], sb + ao);
        }
#pragma unroll
        for (int n2 = 0; n2 < 4; ++n2) {
            uint32_t bhf[4];
            uint32_t bo = (uint32_t)((warp_n + n2 * 16 + b_row) * LG_STRIDE + b_col + k16) * 2;
            ldsm_x4(bhf, sb + 2 * LG_BUF - LG_BUF + bo);   // == sb + LG_BUF + bo
#pragma unroll
            for (int mi = 0; mi < 2; ++mi)
#pragma unroll
                for (int t = 0; t < 2; ++t)
                    mma16816(acc[mi][n2 * 2 + t], ah[mi], bhf + 2 * t);
        }
    }

    const int* mrow = mask + b * SEQ;
    bool is_ent = (g < ENT_HEADS);
#pragma unroll
    for (int mi = 0; mi < 2; ++mi) {
#pragma unroll
        for (int h = 0; h < 2; ++h) {
            int m = m0 + warp_m + mi * 16 + (lane >> 2) + h * 8;
            bool pm = (mrow[m] > 0);
            float* orow = out + ((size_t)bh * SEQ + m) * SEQ;
#pragma unroll
            for (int ni = 0; ni < 8; ++ni) {
                int n = n0 + warp_n + ni * 8 + 2 * (lane & 3);
                float v0 = acc[mi][ni][h * 2 + 0];
                float v1 = acc[mi][ni][h * 2 + 1];
                if (!(pm && mrow[n] > 0))     v0 = -CUDART_INF_F;
                if (!(pm && mrow[n + 1] > 0)) v1 = -CUDART_INF_F;
                if (is_ent) {
                    if (m > n)     v0 -= 1e12f;
                    if (m > n + 1) v1 -= 1e12f;
                }
                *(float2*)(orow + n) = make_float2(v0 * 0.125f, v1 * 0.125f);
            }
        }
    }
}

// ---------------- launch ----------------
extern "C" void kernel_launch(void* const* d_in, const int* in_sizes, int n_in,
                              void* d_out, int out_size) {
    const float* x      = (const float*)d_in[0];
    const int*   mask   = (const int*)  d_in[1];
    const int*   xp     = (const int*)  d_in[2];
    const int*   yp     = (const int*)  d_in[3];
    const float* W_ent  = (const float*)d_in[4];
    const float* b_ent  = (const float*)d_in[5];
    const float* W_head = (const float*)d_in[6];
    const float* b_head = (const float*)d_in[7];
    const float* W_tail = (const float*)d_in[8];
    const float* b_tail = (const float*)d_in[9];
    float* out = (float*)d_out;

    cudaFuncSetAttribute(proj_mma_kernel,   cudaFuncAttributeMaxDynamicSharedMemorySize, PJ_SMEM);
    cudaFuncSetAttribute(logits_mma_kernel, cudaFuncAttributeMaxDynamicSharedMemorySize, LG_SMEM);

    rope_table_kernel<<<(MAX_LEN * 16 + 255) / 256, 256>>>();
    convert_x_kernel<<<(TOKENS * HID / 2 + 255) / 256, 256>>>(x);

    dim3 tb(32, 8);
    convert_w_kernel<<<dim3(N_ENT / 32, HID / 32), tb>>>(W_ent,  N_ENT, 0);
    convert_w_kernel<<<dim3(N_REL / 32, HID / 32), tb>>>(W_head, N_REL, N_ENT);
    convert_w_kernel<<<dim3(N_REL / 32, HID / 32), tb>>>(W_tail, N_REL, N_ENT + N_REL);

    proj_mma_kernel<<<dim3(2,  TOKENS / 128), 256, PJ_SMEM>>>(b_ent,  xp, yp, 0,             0);
    proj_mma_kernel<<<dim3(24, TOKENS / 128), 256, PJ_SMEM>>>(b_head, xp, yp, N_ENT,         ENT_HEADS);
    proj_mma_kernel<<<dim3(24, TOKENS / 128), 256, PJ_SMEM>>>(b_tail, xp, yp, N_ENT + N_REL, ENT_HEADS + REL_HEADS);

    logits_mma_kernel<<<dim3(SEQ / 128, SEQ / 128, BH), 256, LG_SMEM>>>(mask, out);
}